// round 15
// baseline (speedup 1.0000x reference)
#include <cuda_runtime.h>
#include <cuda_fp16.h>
#include <math.h>
#include <stdint.h>

#define BB     8192
#define OPTN   16
#define SHRD   22
#define UNIQN  8
#define OBSW   150
#define MROWS  131072

// ---------------- scratch (device globals) -----------------------------------
__device__ __half g_se_h[BB * 256];                 // 4 MB
__device__ float  g_sec[(size_t)BB * 512];          // 16 MB: se @ tw1a^T
__device__ __half g_tw1ah[512 * 256];               // tw1[:, :256]  [n][k]
__device__ __half g_tw1bh[512 * 128];               // tw1[:, 256:]  [n][k]
__device__ __half g_tw2h[256 * 512];
__device__ __half g_uw2h[128 * 128];
__device__ float  g_sw1t[22 * 256];
__device__ float  g_sw2t[256 * 256];
__device__ float  g_uw1t[8 * 128];

__device__ __forceinline__ void mma_f16(float* c, const uint32_t* a, const uint32_t* b) {
    asm volatile(
        "mma.sync.aligned.m16n8k16.row.col.f32.f16.f16.f32 "
        "{%0,%1,%2,%3}, {%4,%5,%6,%7}, {%8,%9}, {%0,%1,%2,%3};"
        : "+f"(c[0]), "+f"(c[1]), "+f"(c[2]), "+f"(c[3])
        : "r"(a[0]), "r"(a[1]), "r"(a[2]), "r"(a[3]), "r"(b[0]), "r"(b[1]));
}

__device__ __forceinline__ void ldmx4(uint32_t* r, uint32_t addr) {
    asm volatile("ldmatrix.sync.aligned.m8n8.x4.shared.b16 {%0,%1,%2,%3}, [%4];"
                 : "=r"(r[0]), "=r"(r[1]), "=r"(r[2]), "=r"(r[3]) : "r"(addr));
}

__device__ __forceinline__ void cpa16(uint32_t s, const void* g) {
    asm volatile("cp.async.cg.shared.global [%0], [%1], 16;" :: "r"(s), "l"(g));
}
#define CPA_COMMIT() asm volatile("cp.async.commit_group;" ::: "memory")
#define CPA_WAIT1()  asm volatile("cp.async.wait_group 1;"  ::: "memory")
#define CPA_WAIT0()  asm volatile("cp.async.wait_group 0;"  ::: "memory")
#define GDC_WAIT()   asm volatile("griddepcontrol.wait;" ::: "memory")
#define GDC_LAUNCH() asm volatile("griddepcontrol.launch_dependents;" ::: "memory")

// ---------------- prep -------------------------------------------------------
__global__ __launch_bounds__(256) void prep_kernel(
    const float* __restrict__ sw1, const float* __restrict__ sw2,
    const float* __restrict__ uw1, const float* __restrict__ uw2,
    const float* __restrict__ tw1, const float* __restrict__ tw2)
{
    int idx = blockIdx.x * 256 + threadIdx.x;
    if (idx < 512 * 384) {
        int n = idx / 384, k = idx - n * 384;
        __half v = __float2half(tw1[idx]);
        if (k < 256) g_tw1ah[n * 256 + k] = v;
        else         g_tw1bh[n * 128 + (k - 256)] = v;
    }
    if (idx < 256 * 512) g_tw2h[idx] = __float2half(tw2[idx]);
    if (idx < 128 * 128) g_uw2h[idx] = __float2half(uw2[idx]);
    if (idx < 256 * 256) { int o = idx / 256, k = idx - o * 256; g_sw2t[k * 256 + o] = sw2[idx]; }
    if (idx < 256 * 22)  { int o = idx / 22,  i = idx - o * 22;  g_sw1t[i * 256 + o] = sw1[idx]; }
    if (idx < 128 * 8)   { int o = idx / 8,   i = idx - o * 8;   g_uw1t[i * 128 + o] = uw1[idx]; }
    GDC_LAUNCH();
}

// ---------------- shared-branch MLP (f32 math, fp16 out) ---------------------
__global__ __launch_bounds__(256) void se_kernel(
    const float* __restrict__ obs,
    const float* __restrict__ sb1, const float* __restrict__ sb2)
{
    __shared__ float xs[32][SHRD];
    __shared__ float h1[32][256];
    const int t = threadIdx.x;
    const int row0 = blockIdx.x * 32;

    for (int l = t; l < 32 * SHRD; l += 256) {
        int r = l / SHRD, c = l - r * SHRD;
        xs[r][c] = obs[(size_t)(row0 + r) * OBSW + c];
    }
    GDC_WAIT();
    __syncthreads();

    float acc[32];
#pragma unroll
    for (int r = 0; r < 32; ++r) acc[r] = 0.f;
    for (int i = 0; i < SHRD; ++i) {
        float wv = g_sw1t[i * 256 + t];
#pragma unroll
        for (int r = 0; r < 32; ++r) acc[r] += wv * xs[r][i];
    }
    float b1 = sb1[t];
#pragma unroll
    for (int r = 0; r < 32; ++r) h1[r][t] = fmaxf(acc[r] + b1, 0.f);
    __syncthreads();

#pragma unroll
    for (int r = 0; r < 32; ++r) acc[r] = 0.f;
    for (int k = 0; k < 256; ++k) {
        float wv = g_sw2t[k * 256 + t];
#pragma unroll
        for (int r = 0; r < 32; ++r) acc[r] += wv * h1[r][k];
    }
    float b2 = sb2[t];
#pragma unroll
    for (int r = 0; r < 32; ++r)
        g_se_h[(size_t)(row0 + r) * 256 + t] = __float2half(fmaxf(acc[r] + b2, 0.f));
    GDC_LAUNCH();
}

// ---------------- sec = se @ tw1a^T (M=8192, K=256, N=512), raw f32 ----------
__global__ __launch_bounds__(128) void sec_gemm()
{
    constexpr int LDH = 40;
    constexpr int BUFH = 128 * LDH;

    extern __shared__ __align__(16) __half sm[];
    __half* As = sm;
    __half* Bs = sm + 3 * BUFH;

    const int tid  = threadIdx.x;
    const int lane = tid & 31;
    const int wid  = tid >> 5;
    const int wm   = (wid >> 1) * 64;
    const int wn   = (wid & 1) * 64;
    const int mB   = blockIdx.y * 128;
    const int nB   = blockIdx.x * 128;
    const int gID  = lane >> 2;
    const int tIG  = lane & 3;
    const int q    = lane >> 3;
    const int r    = lane & 7;

    const uint32_t AsB = (uint32_t)__cvta_generic_to_shared(As);
    const uint32_t BsB = (uint32_t)__cvta_generic_to_shared(Bs);
    const uint32_t aOff = ((wm + ((q & 1) << 3) + r) * LDH + ((q >> 1) << 3)) * 2;
    const uint32_t bOff = ((wn + ((q >> 1) << 3) + r) * LDH + ((q & 1) << 3)) * 2;

    float acc[4][8][4] = {};
    const int arow = tid >> 2, kq4 = tid & 3;

    auto issue = [&](int it) {
        const int buf = it % 3;
        const int k = it * 32 + kq4 * 8;
#pragma unroll
        for (int j = 0; j < 4; ++j) {
            int row = arow + 32 * j;
            cpa16(AsB + (buf * BUFH + row * LDH + kq4 * 8) * 2,
                  g_se_h + (size_t)(mB + row) * 256 + k);
            cpa16(BsB + (buf * BUFH + row * LDH + kq4 * 8) * 2,
                  g_tw1ah + (size_t)(nB + row) * 256 + k);
        }
        CPA_COMMIT();
    };

    GDC_WAIT();
    issue(0);
    issue(1);
    for (int it = 0; it < 8; ++it) {
        if (it + 1 < 8) CPA_WAIT1(); else CPA_WAIT0();
        __syncthreads();
        if (it + 2 < 8) issue(it + 2);
        const int cur = it % 3;
        const uint32_t aB = AsB + cur * (BUFH * 2) + aOff;
        const uint32_t bB = BsB + cur * (BUFH * 2) + bOff;
#pragma unroll
        for (int ks = 0; ks < 2; ++ks) {
            uint32_t af[4][4], bf[4][4];
#pragma unroll
            for (int mi = 0; mi < 4; ++mi)
                ldmx4(af[mi], aB + mi * (16 * LDH * 2) + ks * 32);
#pragma unroll
            for (int np = 0; np < 4; ++np)
                ldmx4(bf[np], bB + np * (16 * LDH * 2) + ks * 32);
#pragma unroll
            for (int mi = 0; mi < 4; ++mi)
#pragma unroll
                for (int ni = 0; ni < 8; ++ni)
                    mma_f16(acc[mi][ni], af[mi], &bf[ni >> 1][(ni & 1) * 2]);
        }
    }
#pragma unroll
    for (int mi = 0; mi < 4; ++mi) {
#pragma unroll
        for (int ni = 0; ni < 8; ++ni) {
            int cl = wn + ni * 8 + 2 * tIG;
            int row = mB + wm + mi * 16 + gID;
            int col = nB + cl;
            *(float2*)(g_sec + (size_t)row * 512 + col) =
                make_float2(acc[mi][ni][0], acc[mi][ni][1]);
            *(float2*)(g_sec + (size_t)(row + 8) * 512 + col) =
                make_float2(acc[mi][ni][2], acc[mi][ni][3]);
        }
    }
    GDC_LAUNCH();
}

// ---------------- mega trunk: obs -> ue(phase0) -> t1(smem) -> t2 -> heads ---
// 256 threads, 8 warps (2m x 4n of 64x64). One CTA = 128 rows, full network.
// Smem: T1 16 chunks (160KB; chunks 0-3 = h1 staging, chunk 4 = obs staging,
// chunks 8-11 = resident ue during phase 1) + B pipe 3 x 20KB = 220KB.
__global__ __launch_bounds__(256) void mega_trunk(
    const float* __restrict__ obs,
    const float* __restrict__ ub1, const float* __restrict__ ub2,
    const float* __restrict__ noop,
    const float* __restrict__ tb1, const float* __restrict__ tb2,
    const float* __restrict__ vw,  const float* __restrict__ dw,
    const float* __restrict__ vb,  const float* __restrict__ db,
    float* __restrict__ out)
{
    constexpr int LDH = 40;
    constexpr int CH  = 128 * LDH;      // 5120 halfs
    constexpr int BCH = 256 * LDH;      // 10240 halfs

    extern __shared__ __align__(16) __half sm[];
    __half* T1 = sm;                    // 16 * CH
    __half* AR = sm + 8 * CH;           // resident ue (T1 chunks 8..11)
    __half* Bp = sm + 16 * CH;          // 3 * BCH
    float*  xs = (float*)(T1 + 4 * CH); // obs uniq staging [128][8] (chunk 4)
    __shared__ float sb1f[512];
    __shared__ float sb2[256], svw[256], sdw[256];
    __shared__ float sub2[128], sne[128];

    const int tid  = threadIdx.x;
    const int lane = tid & 31;
    const int wid  = tid >> 5;
    const int wm   = (wid >> 2) * 64;
    const int wn   = (wid & 3) * 64;
    const int mB   = blockIdx.x * 128;
    const int gID  = lane >> 2;
    const int tIG  = lane & 3;
    const int q    = lane >> 3;
    const int r    = lane & 7;

    sb1f[tid] = tb1[tid];
    sb1f[256 + tid] = tb1[256 + tid];
    sb2[tid] = tb2[tid];
    svw[tid] = vw[tid];
    sdw[tid] = dw[tid];
    if (tid < 128) { sub2[tid] = ub2[tid]; sne[tid] = noop[tid]; }

    const uint32_t T1B = (uint32_t)__cvta_generic_to_shared(T1);
    const uint32_t ARB = (uint32_t)__cvta_generic_to_shared(AR);
    const uint32_t BpB = (uint32_t)__cvta_generic_to_shared(Bp);
    const uint32_t aOff = ((wm + ((q & 1) << 3) + r) * LDH + ((q >> 1) << 3)) * 2;
    const uint32_t bOff = ((wn + ((q >> 1) << 3) + r) * LDH + ((q & 1) << 3)) * 2;

    const int arow = tid >> 2;          // 0..63
    const int kq4  = tid & 3;

    float acc[4][8][4];

    GDC_WAIT();

    // ======== phase 0: ue = mask(relu(h1 @ uw2^T + ub2)) into AR ============
    // uw2 -> Bp chunks 0..3 (B-pipe is free until phase-1 prefetch)
    {
#pragma unroll
        for (int c = 0; c < 4; ++c) {
            int k = c * 32 + kq4 * 8;
#pragma unroll
            for (int j = 0; j < 2; ++j) {
                int row = arow + 64 * j;
                cpa16(BpB + (c * CH + row * LDH + kq4 * 8) * 2,
                      g_uw2h + (size_t)row * 128 + k);
            }
        }
        CPA_COMMIT();
    }
    // obs uniq gather (float2: element offset always even -> 8B aligned)
    if (tid < 128) {
        int m = mB + tid;
        const float* p = obs + (size_t)(m >> 4) * OBSW + SHRD + (m & 15) * UNIQN;
#pragma unroll
        for (int i = 0; i < 4; ++i) {
            float2 v = *(const float2*)(p + 2 * i);
            xs[tid * 8 + 2 * i]     = v.x;
            xs[tid * 8 + 2 * i + 1] = v.y;
        }
    }
    __syncthreads();

    // h1 = relu(xs @ uw1^T + ub1) -> T1 chunks 0..3 (fp16)
    {
        const int c = tid & 127;
        const int hs = tid >> 7;            // row half: 0-63 / 64-127
        const int chunk = c >> 5, cc = c & 31;
        float w[UNIQN];
#pragma unroll
        for (int i = 0; i < UNIQN; ++i) w[i] = g_uw1t[i * 128 + c];
        float b1 = ub1[c];
#pragma unroll
        for (int pass = 0; pass < 2; ++pass) {
            int r0 = hs * 64 + pass * 32;
            float a32[32];
#pragma unroll
            for (int rr = 0; rr < 32; ++rr) a32[rr] = b1;
#pragma unroll
            for (int i = 0; i < UNIQN; ++i)
#pragma unroll
                for (int rr = 0; rr < 32; ++rr)
                    a32[rr] += w[i] * xs[(r0 + rr) * 8 + i];
#pragma unroll
            for (int rr = 0; rr < 32; ++rr)
                T1[chunk * CH + (r0 + rr) * LDH + cc] =
                    __float2half(fmaxf(a32[rr], 0.f));
        }
    }
    CPA_WAIT0();
    __syncthreads();

    // phase-0 MMA: N=128 -> only warps with wn < 128 are active
    const bool uact = (wn < 128);
    if (uact) {
#pragma unroll
        for (int mi = 0; mi < 4; ++mi)
#pragma unroll
            for (int ni = 0; ni < 8; ++ni)
#pragma unroll
                for (int c4 = 0; c4 < 4; ++c4) acc[mi][ni][c4] = 0.f;
#pragma unroll
        for (int kc = 0; kc < 4; ++kc) {
            const uint32_t aB = T1B + kc * (CH * 2) + aOff;
            const uint32_t bB = BpB + kc * (CH * 2) + bOff;
#pragma unroll
            for (int ks = 0; ks < 2; ++ks) {
                uint32_t af[4][4], bf[4][4];
#pragma unroll
                for (int mi = 0; mi < 4; ++mi)
                    ldmx4(af[mi], aB + mi * (16 * LDH * 2) + ks * 32);
#pragma unroll
                for (int np = 0; np < 4; ++np)
                    ldmx4(bf[np], bB + np * (16 * LDH * 2) + ks * 32);
#pragma unroll
                for (int mi = 0; mi < 4; ++mi)
#pragma unroll
                    for (int ni = 0; ni < 8; ++ni)
                        mma_f16(acc[mi][ni], af[mi], &bf[ni >> 1][(ni & 1) * 2]);
            }
        }
    }
    __syncthreads();    // all reads of Bp(uw2)/T1 0-3 done before reuse

    // ======== phase 1 B prefetch can start now (Bp is free) ==================
    auto issueB1 = [&](int i) {       // i in [0,8): h = i>>2, kc = i&3
        const int buf = i % 3;
        const int k = (i & 3) * 32 + kq4 * 8;
        const int nbase = (i >> 2) * 256;
#pragma unroll
        for (int j = 0; j < 4; ++j) {
            int row = arow + 64 * j;
            cpa16(BpB + (buf * BCH + row * LDH + kq4 * 8) * 2,
                  g_tw1bh + (size_t)(nbase + row) * 128 + k);
        }
        CPA_COMMIT();
    };
    issueB1(0);
    issueB1(1);

    // phase-0 epilogue: bias + relu + no-op mask -> fp16 -> AR (T1 8-11)
    if (uact) {
        bool flg[4][2];
#pragma unroll
        for (int mi = 0; mi < 4; ++mi)
#pragma unroll
            for (int rh = 0; rh < 2; ++rh) {
                int lrow = wm + mi * 16 + rh * 8 + gID;
                flg[mi][rh] = (xs[lrow * 8] == 1.0f);
            }
#pragma unroll
        for (int mi = 0; mi < 4; ++mi) {
#pragma unroll
            for (int ni = 0; ni < 8; ++ni) {
                int cl = wn + ni * 8 + 2 * tIG;     // 0..126
                float b0 = sub2[cl], b1 = sub2[cl + 1];
                float e0 = sne[cl],  e1 = sne[cl + 1];
                int chunk = cl >> 5;
                int cm = cl & 31;
                int row = wm + mi * 16 + gID;
                float v00 = flg[mi][0] ? e0 : fmaxf(acc[mi][ni][0] + b0, 0.f);
                float v01 = flg[mi][0] ? e1 : fmaxf(acc[mi][ni][1] + b1, 0.f);
                float v10 = flg[mi][1] ? e0 : fmaxf(acc[mi][ni][2] + b0, 0.f);
                float v11 = flg[mi][1] ? e1 : fmaxf(acc[mi][ni][3] + b1, 0.f);
                *(__half2*)(AR + chunk * CH + row * LDH + cm)       = __floats2half2_rn(v00, v01);
                *(__half2*)(AR + chunk * CH + (row + 8) * LDH + cm) = __floats2half2_rn(v10, v11);
            }
        }
    }
    // AR writes are ordered before phase-1 reads by the first in-loop barrier

    // ======== phase 1: t1 = relu(ue @ tw1b^T + sec + tb1), 2 N-halves ========
    for (int h = 0; h < 2; ++h) {
#pragma unroll
        for (int mi = 0; mi < 4; ++mi)
#pragma unroll
            for (int ni = 0; ni < 8; ++ni)
#pragma unroll
                for (int c4 = 0; c4 < 4; ++c4) acc[mi][ni][c4] = 0.f;

        for (int kc = 0; kc < 4; ++kc) {
            const int i = h * 4 + kc;
            if (i < 7) CPA_WAIT1(); else CPA_WAIT0();
            __syncthreads();
            if (i + 2 < 8) issueB1(i + 2);
            const uint32_t aB = ARB + kc * (CH * 2) + aOff;
            const uint32_t bB = BpB + (i % 3) * (BCH * 2) + bOff;
#pragma unroll
            for (int ks = 0; ks < 2; ++ks) {
                uint32_t af[4][4], bf[4][4];
#pragma unroll
                for (int mi = 0; mi < 4; ++mi)
                    ldmx4(af[mi], aB + mi * (16 * LDH * 2) + ks * 32);
#pragma unroll
                for (int np = 0; np < 4; ++np)
                    ldmx4(bf[np], bB + np * (16 * LDH * 2) + ks * 32);
#pragma unroll
                for (int mi = 0; mi < 4; ++mi)
#pragma unroll
                    for (int ni = 0; ni < 8; ++ni)
                        mma_f16(acc[mi][ni], af[mi], &bf[ni >> 1][(ni & 1) * 2]);
            }
        }
        __syncthreads();   // AR/buffer reads done before T1 epilogue overwrite

        // epilogue: + sec + bias, relu -> fp16 -> T1 chunks [h*8, h*8+8)
#pragma unroll
        for (int mi = 0; mi < 4; ++mi) {
#pragma unroll
            for (int ni = 0; ni < 8; ++ni) {
                int coll = wn + ni * 8 + 2 * tIG;
                int colg = h * 256 + coll;
                float b0 = sb1f[colg], b1 = sb1f[colg + 1];
                int chunk = colg >> 5;
                int cm = coll & 31;
                int row = wm + mi * 16 + gID;
                float2 s0 = *(const float2*)(g_sec + (size_t)((mB + row) >> 4) * 512 + colg);
                float2 s1 = *(const float2*)(g_sec + (size_t)((mB + row + 8) >> 4) * 512 + colg);
                __half2 h0 = __floats2half2_rn(fmaxf(acc[mi][ni][0] + s0.x + b0, 0.f),
                                               fmaxf(acc[mi][ni][1] + s0.y + b1, 0.f));
                __half2 h1 = __floats2half2_rn(fmaxf(acc[mi][ni][2] + s1.x + b0, 0.f),
                                               fmaxf(acc[mi][ni][3] + s1.y + b1, 0.f));
                *(__half2*)(T1 + chunk * CH + row * LDH + cm)       = h0;
                *(__half2*)(T1 + chunk * CH + (row + 8) * LDH + cm) = h1;
            }
        }
        __syncthreads();
    }

    // ======== phase 2: t2 = relu(t1 @ tw2^T + tb2) + heads ===================
#pragma unroll
    for (int mi = 0; mi < 4; ++mi)
#pragma unroll
        for (int ni = 0; ni < 8; ++ni)
#pragma unroll
            for (int c4 = 0; c4 < 4; ++c4) acc[mi][ni][c4] = 0.f;

    auto issue2 = [&](int it) {
        const int buf = it % 3;
        const int k = it * 32 + kq4 * 8;
#pragma unroll
        for (int j = 0; j < 4; ++j) {
            int row = arow + 64 * j;
            cpa16(BpB + (buf * BCH + row * LDH + kq4 * 8) * 2,
                  g_tw2h + (size_t)row * 512 + k);
        }
        CPA_COMMIT();
    };

    issue2(0);
    issue2(1);
    for (int it = 0; it < 16; ++it) {
        if (it < 15) CPA_WAIT1(); else CPA_WAIT0();
        __syncthreads();
        if (it + 2 < 16) issue2(it + 2);
        const uint32_t aB = T1B + it * (CH * 2) + aOff;
        const uint32_t bB = BpB + (it % 3) * (BCH * 2) + bOff;
#pragma unroll
        for (int ks = 0; ks < 2; ++ks) {
            uint32_t af[4][4], bf[4][4];
#pragma unroll
            for (int mi = 0; mi < 4; ++mi)
                ldmx4(af[mi], aB + mi * (16 * LDH * 2) + ks * 32);
#pragma unroll
            for (int np = 0; np < 4; ++np)
                ldmx4(bf[np], bB + np * (16 * LDH * 2) + ks * 32);
#pragma unroll
            for (int mi = 0; mi < 4; ++mi)
#pragma unroll
                for (int ni = 0; ni < 8; ++ni)
                    mma_f16(acc[mi][ni], af[mi], &bf[ni >> 1][(ni & 1) * 2]);
        }
    }

    // heads over full N=256 -> final outputs
    float pv[8] = {}, pd[8] = {};
#pragma unroll
    for (int mi = 0; mi < 4; ++mi) {
#pragma unroll
        for (int ni = 0; ni < 8; ++ni) {
            int cl = wn + ni * 8 + 2 * tIG;
            float b0 = sb2[cl], b1 = sb2[cl + 1];
            float wv0 = svw[cl], wv1 = svw[cl + 1];
            float wd0 = sdw[cl], wd1 = sdw[cl + 1];
            float t0 = fmaxf(acc[mi][ni][0] + b0, 0.f);
            float t1 = fmaxf(acc[mi][ni][1] + b1, 0.f);
            float t2 = fmaxf(acc[mi][ni][2] + b0, 0.f);
            float t3 = fmaxf(acc[mi][ni][3] + b1, 0.f);
            pv[mi * 2]     += t0 * wv0 + t1 * wv1;
            pd[mi * 2]     += t0 * wd0 + t1 * wd1;
            pv[mi * 2 + 1] += t2 * wv0 + t3 * wv1;
            pd[mi * 2 + 1] += t2 * wd0 + t3 * wd1;
        }
    }
#pragma unroll
    for (int off = 1; off <= 2; off <<= 1) {
#pragma unroll
        for (int i = 0; i < 8; ++i) {
            pv[i] += __shfl_xor_sync(0xffffffffu, pv[i], off);
            pd[i] += __shfl_xor_sync(0xffffffffu, pd[i], off);
        }
    }
    __syncthreads();
    float* stV = (float*)Bp;
    float* stD = stV + 512;
    if (tIG == 0) {
#pragma unroll
        for (int mi = 0; mi < 4; ++mi)
#pragma unroll
            for (int rh = 0; rh < 2; ++rh) {
                int row = wm + mi * 16 + rh * 8 + gID;
                stV[(wid & 3) * 128 + row] = pv[mi * 2 + rh];
                stD[(wid & 3) * 128 + row] = pd[mi * 2 + rh];
            }
    }
    __syncthreads();
    if (tid < 128) {
        float v = stV[tid] + stV[128 + tid] + stV[256 + tid] + stV[384 + tid];
        float d = stD[tid] + stD[128 + tid] + stD[256 + tid] + stD[384 + tid];
        int mm = mB + tid;
        out[mm] = v + vb[0];
        float s = d + db[0];
        out[MROWS + mm] = 1.f / (1.f + expf(-s)) * 0.4f + 0.1f;
    }
    GDC_LAUNCH();
}

// ---------------- launch -----------------------------------------------------
extern "C" void kernel_launch(void* const* d_in, const int* in_sizes, int n_in,
                              void* d_out, int out_size)
{
    (void)in_sizes; (void)n_in; (void)out_size;
    const float* obs  = (const float*)d_in[0];
    const float* sw1  = (const float*)d_in[1];
    const float* sb1  = (const float*)d_in[2];
    const float* sw2  = (const float*)d_in[3];
    const float* sb2  = (const float*)d_in[4];
    const float* uw1  = (const float*)d_in[5];
    const float* ub1  = (const float*)d_in[6];
    const float* uw2  = (const float*)d_in[7];
    const float* ub2  = (const float*)d_in[8];
    const float* noop = (const float*)d_in[9];
    const float* tw1  = (const float*)d_in[10];
    const float* tb1  = (const float*)d_in[11];
    const float* tw2  = (const float*)d_in[12];
    const float* tb2  = (const float*)d_in[13];
    const float* vw   = (const float*)d_in[14];
    const float* vb   = (const float*)d_in[15];
    const float* dw   = (const float*)d_in[16];
    const float* db   = (const float*)d_in[17];
    float* out = (float*)d_out;

    const int smemG = 6 * 128 * 40 * 2;              // 61440
    const int smemM = (16 * 5120 + 3 * 10240) * 2;   // 225280
    static bool attr_done = false;
    if (!attr_done) {
        cudaFuncSetAttribute(sec_gemm,   cudaFuncAttributeMaxDynamicSharedMemorySize, smemG);
        cudaFuncSetAttribute(mega_trunk, cudaFuncAttributeMaxDynamicSharedMemorySize, smemM);
        attr_done = true;
    }

    cudaLaunchAttribute at[1];
    at[0].id = cudaLaunchAttributeProgrammaticStreamSerialization;
    at[0].val.programmaticStreamSerializationAllowed = 1;

    auto mkcfg = [&](dim3 g, dim3 b, int smem) {
        cudaLaunchConfig_t c = {};
        c.gridDim = g; c.blockDim = b; c.dynamicSmemBytes = (size_t)smem;
        c.stream = 0; c.attrs = at; c.numAttrs = 1;
        return c;
    };

    {
        cudaLaunchConfig_t c = mkcfg(dim3(768), dim3(256), 0);
        cudaLaunchKernelEx(&c, prep_kernel, sw1, sw2, uw1, uw2, tw1, tw2);
    }
    {
        cudaLaunchConfig_t c = mkcfg(dim3(BB / 32), dim3(256), 0);
        cudaLaunchKernelEx(&c, se_kernel, obs, sb1, sb2);
    }
    {
        cudaLaunchConfig_t c = mkcfg(dim3(4, BB / 128), dim3(128), smemG);
        cudaLaunchKernelEx(&c, sec_gemm);
    }
    {
        cudaLaunchConfig_t c = mkcfg(dim3(MROWS / 128), dim3(256), smemM);
        cudaLaunchKernelEx(&c, mega_trunk, obs, ub1, ub2, noop,
                           tb1, tb2, vw, dw, vb, db, out);
    }
}

// round 16
// speedup vs baseline: 1.1090x; 1.1090x over previous
#include <cuda_runtime.h>
#include <cuda_fp16.h>
#include <math.h>
#include <stdint.h>

#define BB     8192
#define OPTN   16
#define SHRD   22
#define UNIQN  8
#define OBSW   150
#define MROWS  131072

// ---------------- scratch (device globals) -----------------------------------
__device__ __half g_se_h[BB * 256];                 // 4 MB
__device__ float  g_sec[(size_t)BB * 512];          // 16 MB: se @ tw1a^T
__device__ __half g_tw1ah[512 * 256];               // tw1[:, :256]  [n][k]
__device__ __half g_tw1bh[512 * 128];               // tw1[:, 256:]  [n][k]
__device__ __half g_tw2h[256 * 512];
__device__ __half g_uw2h[128 * 128];
__device__ float  g_sw1t[22 * 256];
__device__ float  g_sw2t[256 * 256];
__device__ float  g_uw1t[8 * 128];

__device__ __forceinline__ void mma_f16(float* c, const uint32_t* a, const uint32_t* b) {
    asm volatile(
        "mma.sync.aligned.m16n8k16.row.col.f32.f16.f16.f32 "
        "{%0,%1,%2,%3}, {%4,%5,%6,%7}, {%8,%9}, {%0,%1,%2,%3};"
        : "+f"(c[0]), "+f"(c[1]), "+f"(c[2]), "+f"(c[3])
        : "r"(a[0]), "r"(a[1]), "r"(a[2]), "r"(a[3]), "r"(b[0]), "r"(b[1]));
}

__device__ __forceinline__ void ldmx4(uint32_t* r, uint32_t addr) {
    asm volatile("ldmatrix.sync.aligned.m8n8.x4.shared.b16 {%0,%1,%2,%3}, [%4];"
                 : "=r"(r[0]), "=r"(r[1]), "=r"(r[2]), "=r"(r[3]) : "r"(addr));
}

__device__ __forceinline__ void cpa16(uint32_t s, const void* g) {
    asm volatile("cp.async.cg.shared.global [%0], [%1], 16;" :: "r"(s), "l"(g));
}
#define CPA_COMMIT() asm volatile("cp.async.commit_group;" ::: "memory")
#define CPA_WAIT1()  asm volatile("cp.async.wait_group 1;"  ::: "memory")
#define CPA_WAIT0()  asm volatile("cp.async.wait_group 0;"  ::: "memory")
#define GDC_WAIT()   asm volatile("griddepcontrol.wait;" ::: "memory")
#define GDC_LAUNCH() asm volatile("griddepcontrol.launch_dependents;" ::: "memory")

// ---------------- prep -------------------------------------------------------
__global__ __launch_bounds__(256) void prep_kernel(
    const float* __restrict__ sw1, const float* __restrict__ sw2,
    const float* __restrict__ uw1, const float* __restrict__ uw2,
    const float* __restrict__ tw1, const float* __restrict__ tw2)
{
    int idx = blockIdx.x * 256 + threadIdx.x;
    if (idx < 512 * 384) {
        int n = idx / 384, k = idx - n * 384;
        __half v = __float2half(tw1[idx]);
        if (k < 256) g_tw1ah[n * 256 + k] = v;
        else         g_tw1bh[n * 128 + (k - 256)] = v;
    }
    if (idx < 256 * 512) g_tw2h[idx] = __float2half(tw2[idx]);
    if (idx < 128 * 128) g_uw2h[idx] = __float2half(uw2[idx]);
    if (idx < 256 * 256) { int o = idx / 256, k = idx - o * 256; g_sw2t[k * 256 + o] = sw2[idx]; }
    if (idx < 256 * 22)  { int o = idx / 22,  i = idx - o * 22;  g_sw1t[i * 256 + o] = sw1[idx]; }
    if (idx < 128 * 8)   { int o = idx / 8,   i = idx - o * 8;   g_uw1t[i * 128 + o] = uw1[idx]; }
    GDC_LAUNCH();
}

// ---------------- shared-branch MLP (f32 math, fp16 out) ---------------------
__global__ __launch_bounds__(256) void se_kernel(
    const float* __restrict__ obs,
    const float* __restrict__ sb1, const float* __restrict__ sb2)
{
    __shared__ float xs[32][SHRD];
    __shared__ float h1[32][256];
    const int t = threadIdx.x;
    const int row0 = blockIdx.x * 32;

    for (int l = t; l < 32 * SHRD; l += 256) {
        int r = l / SHRD, c = l - r * SHRD;
        xs[r][c] = obs[(size_t)(row0 + r) * OBSW + c];
    }
    GDC_WAIT();
    __syncthreads();

    float acc[32];
#pragma unroll
    for (int r = 0; r < 32; ++r) acc[r] = 0.f;
    for (int i = 0; i < SHRD; ++i) {
        float wv = g_sw1t[i * 256 + t];
#pragma unroll
        for (int r = 0; r < 32; ++r) acc[r] += wv * xs[r][i];
    }
    float b1 = sb1[t];
#pragma unroll
    for (int r = 0; r < 32; ++r) h1[r][t] = fmaxf(acc[r] + b1, 0.f);
    __syncthreads();

#pragma unroll
    for (int r = 0; r < 32; ++r) acc[r] = 0.f;
    for (int k = 0; k < 256; ++k) {
        float wv = g_sw2t[k * 256 + t];
#pragma unroll
        for (int r = 0; r < 32; ++r) acc[r] += wv * h1[r][k];
    }
    float b2 = sb2[t];
#pragma unroll
    for (int r = 0; r < 32; ++r)
        g_se_h[(size_t)(row0 + r) * 256 + t] = __float2half(fmaxf(acc[r] + b2, 0.f));
    GDC_LAUNCH();
}

// ---------------- sec = se @ tw1a^T (M=8192, K=256, N=512), raw f32 ----------
__global__ __launch_bounds__(128) void sec_gemm()
{
    constexpr int LDH = 40;
    constexpr int BUFH = 128 * LDH;

    extern __shared__ __align__(16) __half sm[];
    __half* As = sm;
    __half* Bs = sm + 3 * BUFH;

    const int tid  = threadIdx.x;
    const int lane = tid & 31;
    const int wid  = tid >> 5;
    const int wm   = (wid >> 1) * 64;
    const int wn   = (wid & 1) * 64;
    const int mB   = blockIdx.y * 128;
    const int nB   = blockIdx.x * 128;
    const int gID  = lane >> 2;
    const int tIG  = lane & 3;
    const int q    = lane >> 3;
    const int r    = lane & 7;

    const uint32_t AsB = (uint32_t)__cvta_generic_to_shared(As);
    const uint32_t BsB = (uint32_t)__cvta_generic_to_shared(Bs);
    const uint32_t aOff = ((wm + ((q & 1) << 3) + r) * LDH + ((q >> 1) << 3)) * 2;
    const uint32_t bOff = ((wn + ((q >> 1) << 3) + r) * LDH + ((q & 1) << 3)) * 2;

    float acc[4][8][4] = {};
    const int arow = tid >> 2, kq4 = tid & 3;

    auto issue = [&](int it) {
        const int buf = it % 3;
        const int k = it * 32 + kq4 * 8;
#pragma unroll
        for (int j = 0; j < 4; ++j) {
            int row = arow + 32 * j;
            cpa16(AsB + (buf * BUFH + row * LDH + kq4 * 8) * 2,
                  g_se_h + (size_t)(mB + row) * 256 + k);
            cpa16(BsB + (buf * BUFH + row * LDH + kq4 * 8) * 2,
                  g_tw1ah + (size_t)(nB + row) * 256 + k);
        }
        CPA_COMMIT();
    };

    GDC_WAIT();
    issue(0);
    issue(1);
    for (int it = 0; it < 8; ++it) {
        if (it + 1 < 8) CPA_WAIT1(); else CPA_WAIT0();
        __syncthreads();
        if (it + 2 < 8) issue(it + 2);
        const int cur = it % 3;
        const uint32_t aB = AsB + cur * (BUFH * 2) + aOff;
        const uint32_t bB = BsB + cur * (BUFH * 2) + bOff;
#pragma unroll
        for (int ks = 0; ks < 2; ++ks) {
            uint32_t af[4][4], bf[4][4];
#pragma unroll
            for (int mi = 0; mi < 4; ++mi)
                ldmx4(af[mi], aB + mi * (16 * LDH * 2) + ks * 32);
#pragma unroll
            for (int np = 0; np < 4; ++np)
                ldmx4(bf[np], bB + np * (16 * LDH * 2) + ks * 32);
#pragma unroll
            for (int mi = 0; mi < 4; ++mi)
#pragma unroll
                for (int ni = 0; ni < 8; ++ni)
                    mma_f16(acc[mi][ni], af[mi], &bf[ni >> 1][(ni & 1) * 2]);
        }
    }
#pragma unroll
    for (int mi = 0; mi < 4; ++mi) {
#pragma unroll
        for (int ni = 0; ni < 8; ++ni) {
            int cl = wn + ni * 8 + 2 * tIG;
            int row = mB + wm + mi * 16 + gID;
            int col = nB + cl;
            *(float2*)(g_sec + (size_t)row * 512 + col) =
                make_float2(acc[mi][ni][0], acc[mi][ni][1]);
            *(float2*)(g_sec + (size_t)(row + 8) * 512 + col) =
                make_float2(acc[mi][ni][2], acc[mi][ni][3]);
        }
    }
    GDC_LAUNCH();
}

// ---------------- mega trunk: obs -> ue(phase0) -> t1(smem) -> t2 -> heads ---
// 512 threads, 16 warps (2m x 8n of 64x32). One CTA = 128 rows, full network.
// Smem: T1 16 chunks (160KB; chunks 0-3 = h1 staging, chunk 4 = obs staging,
// chunks 8-11 = resident ue during phase 1) + B pipe 3 x 20KB = 220KB.
__global__ __launch_bounds__(512) void mega_trunk(
    const float* __restrict__ obs,
    const float* __restrict__ ub1, const float* __restrict__ ub2,
    const float* __restrict__ noop,
    const float* __restrict__ tb1, const float* __restrict__ tb2,
    const float* __restrict__ vw,  const float* __restrict__ dw,
    const float* __restrict__ vb,  const float* __restrict__ db,
    float* __restrict__ out)
{
    constexpr int LDH = 40;
    constexpr int CH  = 128 * LDH;      // 5120 halfs
    constexpr int BCH = 256 * LDH;      // 10240 halfs

    extern __shared__ __align__(16) __half sm[];
    __half* T1 = sm;                    // 16 * CH
    __half* AR = sm + 8 * CH;           // resident ue (T1 chunks 8..11)
    __half* Bp = sm + 16 * CH;          // 3 * BCH
    float*  xs = (float*)(T1 + 4 * CH); // obs uniq staging [128][8] (chunk 4)
    __shared__ float sb1f[512];
    __shared__ float sb2[256], svw[256], sdw[256];
    __shared__ float sub2[128], sne[128];

    const int tid  = threadIdx.x;
    const int lane = tid & 31;
    const int wid  = tid >> 5;          // 0..15
    const int wm   = (wid >> 3) * 64;   // 2 m-warps
    const int wn   = (wid & 7) * 32;    // 8 n-warps
    const int mB   = blockIdx.x * 128;
    const int gID  = lane >> 2;
    const int tIG  = lane & 3;
    const int q    = lane >> 3;
    const int r    = lane & 7;

    if (tid < 512) sb1f[tid < 512 ? tid : 0] = tb1[tid];
    if (tid < 256) { sb2[tid] = tb2[tid]; svw[tid] = vw[tid]; sdw[tid] = dw[tid]; }
    if (tid < 128) { sub2[tid] = ub2[tid]; sne[tid] = noop[tid]; }

    const uint32_t T1B = (uint32_t)__cvta_generic_to_shared(T1);
    const uint32_t ARB = (uint32_t)__cvta_generic_to_shared(AR);
    const uint32_t BpB = (uint32_t)__cvta_generic_to_shared(Bp);
    const uint32_t aOff = ((wm + ((q & 1) << 3) + r) * LDH + ((q >> 1) << 3)) * 2;
    const uint32_t bOff = ((wn + ((q >> 1) << 3) + r) * LDH + ((q & 1) << 3)) * 2;

    const int arow = tid >> 2;          // 0..127
    const int kq4  = tid & 3;

    float acc[4][4][4];

    GDC_WAIT();

    // ======== phase 0: ue = mask(relu(h1 @ uw2^T + ub2)) into AR ============
    {
#pragma unroll
        for (int c = 0; c < 4; ++c) {
            int k = c * 32 + kq4 * 8;
            cpa16(BpB + (c * CH + arow * LDH + kq4 * 8) * 2,
                  g_uw2h + (size_t)arow * 128 + k);
        }
        CPA_COMMIT();
    }
    if (tid < 128) {
        int m = mB + tid;
        const float* p = obs + (size_t)(m >> 4) * OBSW + SHRD + (m & 15) * UNIQN;
#pragma unroll
        for (int i = 0; i < 4; ++i) {
            float2 v = *(const float2*)(p + 2 * i);
            xs[tid * 8 + 2 * i]     = v.x;
            xs[tid * 8 + 2 * i + 1] = v.y;
        }
    }
    __syncthreads();

    // h1 = relu(xs @ uw1^T + ub1) -> T1 chunks 0..3 (fp16); 512 thr, 1 pass
    {
        const int c = tid & 127;
        const int quarter = tid >> 7;       // 0..3 -> 32-row slice
        const int chunk = c >> 5, cc = c & 31;
        float w[UNIQN];
#pragma unroll
        for (int i = 0; i < UNIQN; ++i) w[i] = g_uw1t[i * 128 + c];
        float b1 = ub1[c];
        int r0 = quarter * 32;
        float a32[32];
#pragma unroll
        for (int rr = 0; rr < 32; ++rr) a32[rr] = b1;
#pragma unroll
        for (int i = 0; i < UNIQN; ++i)
#pragma unroll
            for (int rr = 0; rr < 32; ++rr)
                a32[rr] += w[i] * xs[(r0 + rr) * 8 + i];
#pragma unroll
        for (int rr = 0; rr < 32; ++rr)
            T1[chunk * CH + (r0 + rr) * LDH + cc] =
                __float2half(fmaxf(a32[rr], 0.f));
    }
    CPA_WAIT0();
    __syncthreads();

    // phase-0 MMA: N=128 -> warps with wn < 128 active (8 of 16)
    const bool uact = (wn < 128);
    if (uact) {
#pragma unroll
        for (int mi = 0; mi < 4; ++mi)
#pragma unroll
            for (int ni = 0; ni < 4; ++ni)
#pragma unroll
                for (int c4 = 0; c4 < 4; ++c4) acc[mi][ni][c4] = 0.f;
#pragma unroll
        for (int kc = 0; kc < 4; ++kc) {
            const uint32_t aB = T1B + kc * (CH * 2) + aOff;
            const uint32_t bB = BpB + kc * (CH * 2) + bOff;
#pragma unroll
            for (int ks = 0; ks < 2; ++ks) {
                uint32_t af[4][4], bf[2][4];
#pragma unroll
                for (int mi = 0; mi < 4; ++mi)
                    ldmx4(af[mi], aB + mi * (16 * LDH * 2) + ks * 32);
#pragma unroll
                for (int np = 0; np < 2; ++np)
                    ldmx4(bf[np], bB + np * (16 * LDH * 2) + ks * 32);
#pragma unroll
                for (int mi = 0; mi < 4; ++mi)
#pragma unroll
                    for (int ni = 0; ni < 4; ++ni)
                        mma_f16(acc[mi][ni], af[mi], &bf[ni >> 1][(ni & 1) * 2]);
            }
        }
    }
    __syncthreads();    // all reads of Bp(uw2)/T1 0-3 done before reuse

    // ======== phase-1 B prefetch (Bp free now) ===============================
    auto issueB1 = [&](int i) {       // i in [0,8): h = i>>2, kc = i&3
        const int buf = i % 3;
        const int k = (i & 3) * 32 + kq4 * 8;
        const int nbase = (i >> 2) * 256;
#pragma unroll
        for (int j = 0; j < 2; ++j) {
            int row = arow + 128 * j;
            cpa16(BpB + (buf * BCH + row * LDH + kq4 * 8) * 2,
                  g_tw1bh + (size_t)(nbase + row) * 128 + k);
        }
        CPA_COMMIT();
    };
    issueB1(0);
    issueB1(1);

    // phase-0 epilogue: bias + relu + no-op mask -> fp16 -> AR (T1 8-11)
    if (uact) {
        bool flg[4][2];
#pragma unroll
        for (int mi = 0; mi < 4; ++mi)
#pragma unroll
            for (int rh = 0; rh < 2; ++rh) {
                int lrow = wm + mi * 16 + rh * 8 + gID;
                flg[mi][rh] = (xs[lrow * 8] == 1.0f);
            }
#pragma unroll
        for (int mi = 0; mi < 4; ++mi) {
#pragma unroll
            for (int ni = 0; ni < 4; ++ni) {
                int cl = wn + ni * 8 + 2 * tIG;     // 0..126
                float b0 = sub2[cl], b1 = sub2[cl + 1];
                float e0 = sne[cl],  e1 = sne[cl + 1];
                int chunk = cl >> 5;
                int cm = cl & 31;
                int row = wm + mi * 16 + gID;
                float v00 = flg[mi][0] ? e0 : fmaxf(acc[mi][ni][0] + b0, 0.f);
                float v01 = flg[mi][0] ? e1 : fmaxf(acc[mi][ni][1] + b1, 0.f);
                float v10 = flg[mi][1] ? e0 : fmaxf(acc[mi][ni][2] + b0, 0.f);
                float v11 = flg[mi][1] ? e1 : fmaxf(acc[mi][ni][3] + b1, 0.f);
                *(__half2*)(AR + chunk * CH + row * LDH + cm)       = __floats2half2_rn(v00, v01);
                *(__half2*)(AR + chunk * CH + (row + 8) * LDH + cm) = __floats2half2_rn(v10, v11);
            }
        }
    }
    // AR writes ordered before phase-1 reads by the first in-loop barrier

    // ======== phase 1: t1 = relu(ue @ tw1b^T + sec + tb1), 2 N-halves ========
    for (int h = 0; h < 2; ++h) {
#pragma unroll
        for (int mi = 0; mi < 4; ++mi)
#pragma unroll
            for (int ni = 0; ni < 4; ++ni)
#pragma unroll
                for (int c4 = 0; c4 < 4; ++c4) acc[mi][ni][c4] = 0.f;

        for (int kc = 0; kc < 4; ++kc) {
            const int i = h * 4 + kc;
            if (i < 7) CPA_WAIT1(); else CPA_WAIT0();
            __syncthreads();
            if (i + 2 < 8) issueB1(i + 2);
            const uint32_t aB = ARB + kc * (CH * 2) + aOff;
            const uint32_t bB = BpB + (i % 3) * (BCH * 2) + bOff;
#pragma unroll
            for (int ks = 0; ks < 2; ++ks) {
                uint32_t af[4][4], bf[2][4];
#pragma unroll
                for (int mi = 0; mi < 4; ++mi)
                    ldmx4(af[mi], aB + mi * (16 * LDH * 2) + ks * 32);
#pragma unroll
                for (int np = 0; np < 2; ++np)
                    ldmx4(bf[np], bB + np * (16 * LDH * 2) + ks * 32);
#pragma unroll
                for (int mi = 0; mi < 4; ++mi)
#pragma unroll
                    for (int ni = 0; ni < 4; ++ni)
                        mma_f16(acc[mi][ni], af[mi], &bf[ni >> 1][(ni & 1) * 2]);
            }
        }
        __syncthreads();   // AR/buffer reads done before T1 epilogue overwrite

        // epilogue: + sec + bias, relu -> fp16 -> T1 chunks [h*8, h*8+8)
#pragma unroll
        for (int mi = 0; mi < 4; ++mi) {
#pragma unroll
            for (int ni = 0; ni < 4; ++ni) {
                int coll = wn + ni * 8 + 2 * tIG;
                int colg = h * 256 + coll;
                float b0 = sb1f[colg], b1 = sb1f[colg + 1];
                int chunk = colg >> 5;
                int cm = coll & 31;
                int row = wm + mi * 16 + gID;
                float2 s0 = *(const float2*)(g_sec + (size_t)((mB + row) >> 4) * 512 + colg);
                float2 s1 = *(const float2*)(g_sec + (size_t)((mB + row + 8) >> 4) * 512 + colg);
                __half2 h0 = __floats2half2_rn(fmaxf(acc[mi][ni][0] + s0.x + b0, 0.f),
                                               fmaxf(acc[mi][ni][1] + s0.y + b1, 0.f));
                __half2 h1 = __floats2half2_rn(fmaxf(acc[mi][ni][2] + s1.x + b0, 0.f),
                                               fmaxf(acc[mi][ni][3] + s1.y + b1, 0.f));
                *(__half2*)(T1 + chunk * CH + row * LDH + cm)       = h0;
                *(__half2*)(T1 + chunk * CH + (row + 8) * LDH + cm) = h1;
            }
        }
        __syncthreads();
    }

    // ======== phase 2: t2 = relu(t1 @ tw2^T + tb2) + heads ===================
#pragma unroll
    for (int mi = 0; mi < 4; ++mi)
#pragma unroll
        for (int ni = 0; ni < 4; ++ni)
#pragma unroll
            for (int c4 = 0; c4 < 4; ++c4) acc[mi][ni][c4] = 0.f;

    auto issue2 = [&](int it) {
        const int buf = it % 3;
        const int k = it * 32 + kq4 * 8;
#pragma unroll
        for (int j = 0; j < 2; ++j) {
            int row = arow + 128 * j;
            cpa16(BpB + (buf * BCH + row * LDH + kq4 * 8) * 2,
                  g_tw2h + (size_t)row * 512 + k);
        }
        CPA_COMMIT();
    };

    issue2(0);
    issue2(1);
    for (int it = 0; it < 16; ++it) {
        if (it < 15) CPA_WAIT1(); else CPA_WAIT0();
        __syncthreads();
        if (it + 2 < 16) issue2(it + 2);
        const uint32_t aB = T1B + it * (CH * 2) + aOff;
        const uint32_t bB = BpB + (it % 3) * (BCH * 2) + bOff;
#pragma unroll
        for (int ks = 0; ks < 2; ++ks) {
            uint32_t af[4][4], bf[2][4];
#pragma unroll
            for (int mi = 0; mi < 4; ++mi)
                ldmx4(af[mi], aB + mi * (16 * LDH * 2) + ks * 32);
#pragma unroll
            for (int np = 0; np < 2; ++np)
                ldmx4(bf[np], bB + np * (16 * LDH * 2) + ks * 32);
#pragma unroll
            for (int mi = 0; mi < 4; ++mi)
#pragma unroll
                for (int ni = 0; ni < 4; ++ni)
                    mma_f16(acc[mi][ni], af[mi], &bf[ni >> 1][(ni & 1) * 2]);
        }
    }

    // heads over full N=256 -> final outputs
    float pv[8] = {}, pd[8] = {};
#pragma unroll
    for (int mi = 0; mi < 4; ++mi) {
#pragma unroll
        for (int ni = 0; ni < 4; ++ni) {
            int cl = wn + ni * 8 + 2 * tIG;
            float b0 = sb2[cl], b1 = sb2[cl + 1];
            float wv0 = svw[cl], wv1 = svw[cl + 1];
            float wd0 = sdw[cl], wd1 = sdw[cl + 1];
            float t0 = fmaxf(acc[mi][ni][0] + b0, 0.f);
            float t1 = fmaxf(acc[mi][ni][1] + b1, 0.f);
            float t2 = fmaxf(acc[mi][ni][2] + b0, 0.f);
            float t3 = fmaxf(acc[mi][ni][3] + b1, 0.f);
            pv[mi * 2]     += t0 * wv0 + t1 * wv1;
            pd[mi * 2]     += t0 * wd0 + t1 * wd1;
            pv[mi * 2 + 1] += t2 * wv0 + t3 * wv1;
            pd[mi * 2 + 1] += t2 * wd0 + t3 * wd1;
        }
    }
#pragma unroll
    for (int off = 1; off <= 2; off <<= 1) {
#pragma unroll
        for (int i = 0; i < 8; ++i) {
            pv[i] += __shfl_xor_sync(0xffffffffu, pv[i], off);
            pd[i] += __shfl_xor_sync(0xffffffffu, pd[i], off);
        }
    }
    __syncthreads();
    float* stV = (float*)Bp;            // 8 x 128 floats
    float* stD = stV + 1024;
    if (tIG == 0) {
#pragma unroll
        for (int mi = 0; mi < 4; ++mi)
#pragma unroll
            for (int rh = 0; rh < 2; ++rh) {
                int row = wm + mi * 16 + rh * 8 + gID;
                stV[(wid & 7) * 128 + row] = pv[mi * 2 + rh];
                stD[(wid & 7) * 128 + row] = pd[mi * 2 + rh];
            }
    }
    __syncthreads();
    if (tid < 128) {
        float v = 0.f, d = 0.f;
#pragma unroll
        for (int s = 0; s < 8; ++s) {
            v += stV[s * 128 + tid];
            d += stD[s * 128 + tid];
        }
        int mm = mB + tid;
        out[mm] = v + vb[0];
        float s = d + db[0];
        out[MROWS + mm] = 1.f / (1.f + expf(-s)) * 0.4f + 0.1f;
    }
    GDC_LAUNCH();
}

// ---------------- launch -----------------------------------------------------
extern "C" void kernel_launch(void* const* d_in, const int* in_sizes, int n_in,
                              void* d_out, int out_size)
{
    (void)in_sizes; (void)n_in; (void)out_size;
    const float* obs  = (const float*)d_in[0];
    const float* sw1  = (const float*)d_in[1];
    const float* sb1  = (const float*)d_in[2];
    const float* sw2  = (const float*)d_in[3];
    const float* sb2  = (const float*)d_in[4];
    const float* uw1  = (const float*)d_in[5];
    const float* ub1  = (const float*)d_in[6];
    const float* uw2  = (const float*)d_in[7];
    const float* ub2  = (const float*)d_in[8];
    const float* noop = (const float*)d_in[9];
    const float* tw1  = (const float*)d_in[10];
    const float* tb1  = (const float*)d_in[11];
    const float* tw2  = (const float*)d_in[12];
    const float* tb2  = (const float*)d_in[13];
    const float* vw   = (const float*)d_in[14];
    const float* vb   = (const float*)d_in[15];
    const float* dw   = (const float*)d_in[16];
    const float* db   = (const float*)d_in[17];
    float* out = (float*)d_out;

    const int smemG = 6 * 128 * 40 * 2;              // 61440
    const int smemM = (16 * 5120 + 3 * 10240) * 2;   // 225280
    static bool attr_done = false;
    if (!attr_done) {
        cudaFuncSetAttribute(sec_gemm,   cudaFuncAttributeMaxDynamicSharedMemorySize, smemG);
        cudaFuncSetAttribute(mega_trunk, cudaFuncAttributeMaxDynamicSharedMemorySize, smemM);
        attr_done = true;
    }

    cudaLaunchAttribute at[1];
    at[0].id = cudaLaunchAttributeProgrammaticStreamSerialization;
    at[0].val.programmaticStreamSerializationAllowed = 1;

    auto mkcfg = [&](dim3 g, dim3 b, int smem) {
        cudaLaunchConfig_t c = {};
        c.gridDim = g; c.blockDim = b; c.dynamicSmemBytes = (size_t)smem;
        c.stream = 0; c.attrs = at; c.numAttrs = 1;
        return c;
    };

    {
        cudaLaunchConfig_t c = mkcfg(dim3(768), dim3(256), 0);
        cudaLaunchKernelEx(&c, prep_kernel, sw1, sw2, uw1, uw2, tw1, tw2);
    }
    {
        cudaLaunchConfig_t c = mkcfg(dim3(BB / 32), dim3(256), 0);
        cudaLaunchKernelEx(&c, se_kernel, obs, sb1, sb2);
    }
    {
        cudaLaunchConfig_t c = mkcfg(dim3(4, BB / 128), dim3(128), smemG);
        cudaLaunchKernelEx(&c, sec_gemm);
    }
    {
        cudaLaunchConfig_t c = mkcfg(dim3(MROWS / 128), dim3(512), smemM);
        cudaLaunchKernelEx(&c, mega_trunk, obs, ub1, ub2, noop,
                           tb1, tb2, vw, dw, vb, db, out);
    }
}